// round 13
// baseline (speedup 1.0000x reference)
#include <cuda_runtime.h>
#include <cuda_fp16.h>
#include <cstdint>
#include <cstddef>

// ---------------- problem dims ----------------
#define NUM_TOKENS 2048
#define HID        4096
#define NLORA      8
#define LRANK      16
#define VOCAB_N    32000
#define KAUG       (HID + NLORA * LRANK)   // 4224

// ---------------- GEMM tiling ----------------
#define BM     128
#define BN     256
#define BK     64                          // 64 fp16 = 128B rows (SW128)
#define KSTEPS (KAUG / BK)                 // 66
#define NSTAGES 4
#define MTILES  (NUM_TOKENS / BM)          // 16
#define NTILES  (VOCAB_N / BN)             // 125

#define A_BYTES (BM * BK * 2)              // 16384
#define B_BYTES (BN * BK * 2)              // 32768
#define STAGE_BYTES (A_BYTES + B_BYTES)    // 49152

#define SM_A_OFF 1024
#define SM_B_OFF (SM_A_OFF + NSTAGES * A_BYTES)     // 66560
#define SM_TOTAL (SM_B_OFF + NSTAGES * B_BYTES)     // 197632 (1 CTA/SM)

// Pre-tiled, pre-swizzled fp16 operand buffers (device-global scratch)
__device__ __align__(1024) unsigned char g_Hs[(size_t)MTILES * KSTEPS * A_BYTES];
__device__ __align__(1024) unsigned char g_Ws[(size_t)NTILES * KSTEPS * B_BYTES];

// ---------------- helpers ----------------
__device__ __forceinline__ uint32_t smem_u32(const void* p) {
    uint32_t a;
    asm("{ .reg .u64 t; cvta.to.shared.u64 t, %1; cvt.u32.u64 %0, t; }" : "=r"(a) : "l"(p));
    return a;
}
__device__ __forceinline__ uint32_t swz128(uint32_t o) { return o ^ ((o >> 3) & 0x70u); }

__device__ __forceinline__ uint32_t h2_bits(__half2 h) {
    union { __half2 h; uint32_t u; } cv;
    cv.h = h;
    return cv.u;
}

#define MBAR_INIT(addr, cnt) \
    asm volatile("mbarrier.init.shared.b64 [%0], %1;" :: "r"(addr), "r"((uint32_t)(cnt)) : "memory")

#define MBAR_EXPECT_TX(addr, bytes) \
    asm volatile("mbarrier.arrive.expect_tx.shared.b64 _, [%0], %1;" :: "r"(addr), "r"((uint32_t)(bytes)) : "memory")

#define MBAR_ARRIVE(addr) \
    asm volatile("mbarrier.arrive.shared.b64 _, [%0];" :: "r"(addr) : "memory")

#define MBAR_WAIT(addr, parity) do {                                                   \
    uint32_t _m = (addr), _p = (uint32_t)(parity), _d;                                 \
    asm volatile("{\n\t.reg .pred p;\n\t"                                              \
        "mbarrier.try_wait.parity.acquire.cta.shared::cta.b64 p, [%1], %2;\n\t"        \
        "selp.b32 %0, 1, 0, p;\n\t}"                                                   \
        : "=r"(_d) : "r"(_m), "r"(_p) : "memory");                                     \
    if (!_d) {                                                                         \
        asm volatile("{\n\t.reg .pred P1;\n\t"                                         \
            "WL_%=:\n\t"                                                               \
            "mbarrier.try_wait.parity.acquire.cta.shared::cta.b64 P1, [%0], %1, 0x989680;\n\t" \
            "@P1 bra.uni WD_%=;\n\t"                                                   \
            "bra.uni WL_%=;\n\t"                                                       \
            "WD_%=:\n\t}" :: "r"(_m), "r"(_p) : "memory");                             \
    }                                                                                  \
} while (0)

__device__ __forceinline__ void bulk_g2s(uint32_t dst, const void* src, uint32_t bytes, uint32_t mbar) {
    asm volatile(
        "cp.async.bulk.shared::cluster.global.mbarrier::complete_tx::bytes [%0], [%1], %2, [%3];"
        :: "r"(dst), "l"(src), "r"(bytes), "r"(mbar) : "memory");
}

#define LDSM_X4(r0, r1, r2, r3, addr)                                                  \
    asm volatile("ldmatrix.sync.aligned.m8n8.x4.shared.b16 {%0,%1,%2,%3}, [%4];"       \
        : "=r"(r0), "=r"(r1), "=r"(r2), "=r"(r3) : "r"(addr))

#define MMA16816(c, a0, a1, a2, a3, b0, b1)                                            \
    asm volatile("mma.sync.aligned.m16n8k16.row.col.f32.f16.f16.f32 "                  \
        "{%0,%1,%2,%3}, {%4,%5,%6,%7}, {%8,%9}, {%0,%1,%2,%3};"                        \
        : "+f"((c)[0]), "+f"((c)[1]), "+f"((c)[2]), "+f"((c)[3])                       \
        : "r"(a0), "r"(a1), "r"(a2), "r"(a3), "r"(b0), "r"(b1))

// ---------------- fused build: W' (blocks 0..15999) + H' (blocks 16000..18047) ----------------
#define WBLOCKS (VOCAB_N / 2)   // 16000

__global__ void __launch_bounds__(256) build_hw(const float* __restrict__ H,
                                                const float* __restrict__ W,
                                                const float* __restrict__ lA,
                                                const float* __restrict__ lB,
                                                const int* __restrict__ idx) {
    int bid = blockIdx.x;
    int tid = threadIdx.x;

    if (bid < WBLOCKS) {
        // ---- W' build: vocab rows 2*bid + (tid>>7), tiles of BN=256 rows ----
        int v = bid * 2 + (tid >> 7);
        int t128 = tid & 127;
        int row = v & (BN - 1);
        unsigned char* blk = g_Ws + (size_t)(v >> 8) * KSTEPS * B_BYTES;
        const float4* Wrow = (const float4*)(W + (size_t)v * HID);

        for (int c8 = t128; c8 < HID / 8; c8 += 128) {
            float4 f0 = Wrow[c8 * 2];
            float4 f1 = Wrow[c8 * 2 + 1];
            int c = c8 * 8;
            int ks = c >> 6, cc = c & 63;
            uint32_t o = swz128((uint32_t)(row * 128 + cc * 2));
            uint4 pk;
            pk.x = h2_bits(__floats2half2_rn(f0.x, f0.y));
            pk.y = h2_bits(__floats2half2_rn(f0.z, f0.w));
            pk.z = h2_bits(__floats2half2_rn(f1.x, f1.y));
            pk.w = h2_bits(__floats2half2_rn(f1.z, f1.w));
            *reinterpret_cast<uint4*>(blk + (size_t)ks * B_BYTES + o) = pk;
        }
        {
            int j = t128;                    // 0..127 -> (e, r)
            int e = j >> 4, r = j & 15;
            float val = lB[((size_t)e * VOCAB_N + v) * LRANK + r];
            int col = HID + j;
            int ks = col >> 6, cc = col & 63;
            *(__half*)(blk + (size_t)ks * B_BYTES + swz128((uint32_t)(row * 128 + cc * 2))) =
                __float2half_rn(val);
        }
        return;
    }

    // ---- H' build: one token, 256 threads ----
    int t = bid - WBLOCKS;
    int e = idx[t];
    const float* Arow = lA + (size_t)e * LRANK * HID;
    unsigned char* blk = g_Hs + (size_t)(t >> 7) * KSTEPS * A_BYTES;
    int row = t & 127;

    float acc[LRANK];
#pragma unroll
    for (int r = 0; r < LRANK; r++) acc[r] = 0.f;

    for (int h = tid; h < HID; h += 256) {
        float x = H[(size_t)t * HID + h];
        int ks = h >> 6, cc = h & 63;
        *(__half*)(blk + (size_t)ks * A_BYTES + swz128((uint32_t)(row * 128 + cc * 2))) =
            __float2half_rn(x);
#pragma unroll
        for (int r = 0; r < LRANK; r++) acc[r] += x * Arow[r * HID + h];
    }

    __shared__ float wsum[8][LRANK];
    __shared__ float xa[LRANK];
    int lane = tid & 31, w = tid >> 5;
#pragma unroll
    for (int r = 0; r < LRANK; r++) {
        float v = acc[r];
        v += __shfl_down_sync(0xffffffffu, v, 16);
        v += __shfl_down_sync(0xffffffffu, v, 8);
        v += __shfl_down_sync(0xffffffffu, v, 4);
        v += __shfl_down_sync(0xffffffffu, v, 2);
        v += __shfl_down_sync(0xffffffffu, v, 1);
        if (lane == 0) wsum[w][r] = v;
    }
    __syncthreads();
    if (tid < LRANK) {
        float v = 0.f;
#pragma unroll
        for (int ww = 0; ww < 8; ww++) v += wsum[ww][tid];
        xa[tid] = v;
    }
    __syncthreads();
    if (tid < NLORA * LRANK) {
        int col = HID + tid;
        float v = ((tid >> 4) == e) ? xa[tid & 15] : 0.f;
        int ks = col >> 6, cc = col & 63;
        *(__half*)(blk + (size_t)ks * A_BYTES + swz128((uint32_t)(row * 128 + cc * 2))) =
            __float2half_rn(v);
    }
}

// ---------------- main GEMM: out[2048,32000] = H' @ W'^T (HMMA fp16, fp32 acc) ----------------
// 256 threads: 8 compute warps (2x4 grid, 64x64 each). ROTATING inline producer:
// stage refill for k-step ks is issued by warp (ks & 7), so the empty-wait skew is
// spread over all warps instead of serializing warp 0 every stage. Early empty-arrive
// at the last stage read (k16==2) further cuts the skew. 2 warps/SMSP, spill-free.
__global__ void __launch_bounds__(256, 1) lmhead_gemm(float* __restrict__ out) {
    extern __shared__ unsigned char smem[];
    uint32_t sb = smem_u32(smem);
    int tid = threadIdx.x, wid = tid >> 5, lane = tid & 31;
    int tile_m = blockIdx.x & (MTILES - 1);    // 16 consecutive bids share one n-tile (L2 reuse)
    int tile_n = blockIdx.x >> 4;

    uint32_t b_full  = sb + 0;     // NSTAGES x 8B
    uint32_t b_empty = sb + 64;    // NSTAGES x 8B

    if (tid == 0) {
        for (int s = 0; s < NSTAGES; s++) {
            MBAR_INIT(b_full + s * 8, 1);
            MBAR_INIT(b_empty + s * 8, 8);   // one arrive per warp
        }
    }
    __syncthreads();

    const unsigned char* gA = g_Hs + (size_t)tile_m * KSTEPS * A_BYTES;
    const unsigned char* gB = g_Ws + (size_t)tile_n * KSTEPS * B_BYTES;

    // prologue prefetch: one thread fills all NSTAGES stages
    if (tid == 0) {
#pragma unroll
        for (int i = 0; i < NSTAGES; i++) {
            MBAR_EXPECT_TX(b_full + i * 8, STAGE_BYTES);
            bulk_g2s(sb + SM_A_OFF + i * A_BYTES, gA + (size_t)i * A_BYTES,
                     A_BYTES, b_full + i * 8);
            bulk_g2s(sb + SM_B_OFF + i * B_BYTES, gB + (size_t)i * B_BYTES,
                     B_BYTES, b_full + i * 8);
        }
    }

    // ---- 2x4 warp grid, each warp 64(m) x 64(n) ----
    int warp_m = wid & 1;          // 0..1 -> 64-row block
    int warp_n = wid >> 1;         // 0..3 -> 64-col block

    float acc[4][8][4];            // 128 regs
#pragma unroll
    for (int a = 0; a < 4; a++)
#pragma unroll
        for (int b = 0; b < 8; b++)
#pragma unroll
            for (int c = 0; c < 4; c++) acc[a][b][c] = 0.f;

    int lrow = lane & 15;
    int lhal = lane >> 4;

    uint32_t af[2][4][4];          // double-buffered A fragments
    uint32_t bf[2][4][4];          // double-buffered B fragments

#define LOAD_FRAGS(buf, ss, kk) do {                                                   \
    uint32_t _ab = sb + SM_A_OFF + (uint32_t)(ss) * A_BYTES;                           \
    uint32_t _bb = sb + SM_B_OFF + (uint32_t)(ss) * B_BYTES;                           \
    _Pragma("unroll")                                                                  \
    for (int _mt = 0; _mt < 4; _mt++) {                                                \
        uint32_t _o = (uint32_t)((warp_m * 64 + _mt * 16 + lrow) * 128 +               \
                                 (kk) * 32 + lhal * 16);                               \
        LDSM_X4(af[buf][_mt][0], af[buf][_mt][1], af[buf][_mt][2], af[buf][_mt][3],    \
                _ab + swz128(_o));                                                     \
    }                                                                                  \
    _Pragma("unroll")                                                                  \
    for (int _p = 0; _p < 4; _p++) {                                                   \
        uint32_t _o = (uint32_t)((warp_n * 64 + _p * 16 + lrow) * 128 +                \
                                 (kk) * 32 + lhal * 16);                               \
        LDSM_X4(bf[buf][_p][0], bf[buf][_p][1], bf[buf][_p][2], bf[buf][_p][3],        \
                _bb + swz128(_o));                                                     \
    }                                                                                  \
} while (0)

#define MMA_ALL(buf) do {                                                              \
    _Pragma("unroll")                                                                  \
    for (int _mt = 0; _mt < 4; _mt++) {                                                \
        _Pragma("unroll")                                                              \
        for (int _p = 0; _p < 4; _p++) {                                               \
            MMA16816(acc[_mt][_p * 2 + 0], af[buf][_mt][0], af[buf][_mt][1],           \
                     af[buf][_mt][2], af[buf][_mt][3], bf[buf][_p][0], bf[buf][_p][2]);\
            MMA16816(acc[_mt][_p * 2 + 1], af[buf][_mt][0], af[buf][_mt][1],           \
                     af[buf][_mt][2], af[buf][_mt][3], bf[buf][_p][1], bf[buf][_p][3]);\
        }                                                                              \
    }                                                                                  \
} while (0)

    // prologue: wait stage 0, load first fragments
    MBAR_WAIT(b_full + 0, 0);
    LOAD_FRAGS(0, 0, 0);

    int s = 0, ph = 0;
    for (int ks = 0; ks < KSTEPS; ks++) {
#pragma unroll
        for (int k16 = 0; k16 < 4; k16++) {
            const int cur = k16 & 1;
            const int nxt = cur ^ 1;
            if (k16 < 3) {
                LOAD_FRAGS(nxt, s, k16 + 1);           // prefetch next k-step, same stage
                if (k16 == 2 && lane == 0)             // last read of stage s done ->
                    MBAR_ARRIVE(b_empty + s * 8);      // early release (arrive = release)
            } else if (ks + 1 < KSTEPS) {
                int s2 = (s + 1 == NSTAGES) ? 0 : s + 1;
                int p2 = (s + 1 == NSTAGES) ? (ph ^ 1) : ph;
                MBAR_WAIT(b_full + s2 * 8, p2);        // hidden behind queued MMAs
                LOAD_FRAGS(nxt, s2, 0);                // prefetch first k-step of next stage
            }
            MMA_ALL(cur);
        }
        // rotating inline producer: warp (ks & 7), lane 0, refills this stage
        if (wid == (ks & 7) && lane == 0 && ks + NSTAGES < KSTEPS) {
            MBAR_WAIT(b_empty + s * 8, (ks / NSTAGES) & 1);
            MBAR_EXPECT_TX(b_full + s * 8, STAGE_BYTES);
            bulk_g2s(sb + SM_A_OFF + s * A_BYTES,
                     gA + (size_t)(ks + NSTAGES) * A_BYTES, A_BYTES, b_full + s * 8);
            bulk_g2s(sb + SM_B_OFF + s * B_BYTES,
                     gB + (size_t)(ks + NSTAGES) * B_BYTES, B_BYTES, b_full + s * 8);
        }
        if (++s == NSTAGES) { s = 0; ph ^= 1; }
    }

    // ---- epilogue: direct fp32 stores ----
    int row_base = tile_m * BM + warp_m * 64 + (lane >> 2);
    int col_base = tile_n * BN + warp_n * 64 + (lane & 3) * 2;
#pragma unroll
    for (int mt = 0; mt < 4; mt++) {
#pragma unroll
        for (int nt = 0; nt < 8; nt++) {
            int col = col_base + nt * 8;
            size_t r0 = (size_t)(row_base + mt * 16) * VOCAB_N + col;
            size_t r1 = r0 + 8 * VOCAB_N;
            *reinterpret_cast<float2*>(out + r0) =
                make_float2(acc[mt][nt][0], acc[mt][nt][1]);
            *reinterpret_cast<float2*>(out + r1) =
                make_float2(acc[mt][nt][2], acc[mt][nt][3]);
        }
    }
}

// ---------------- launch ----------------
extern "C" void kernel_launch(void* const* d_in, const int* in_sizes, int n_in,
                              void* d_out, int out_size) {
    const float* H   = (const float*)d_in[0];   // [2048, 4096]
    const float* W   = (const float*)d_in[1];   // [32000, 4096]
    const float* lA  = (const float*)d_in[2];   // [8, 16, 4096]
    const float* lB  = (const float*)d_in[3];   // [8, 32000, 16]
    const int*   idx = (const int*)d_in[4];     // [2048]
    float* out = (float*)d_out;                 // [2048, 32000]

    cudaFuncSetAttribute(lmhead_gemm, cudaFuncAttributeMaxDynamicSharedMemorySize, SM_TOTAL);

    build_hw<<<WBLOCKS + NUM_TOKENS, 256>>>(H, W, lA, lB, idx);
    lmhead_gemm<<<MTILES * NTILES, 256, SM_TOTAL>>>(out);
}

// round 14
// speedup vs baseline: 1.0410x; 1.0410x over previous
#include <cuda_runtime.h>
#include <cuda_fp16.h>
#include <cstdint>
#include <cstddef>

// ---------------- problem dims ----------------
#define NUM_TOKENS 2048
#define HID        4096
#define NLORA      8
#define LRANK      16
#define VOCAB_N    32000
#define KAUG       (HID + NLORA * LRANK)   // 4224

// ---------------- GEMM tiling (R6 shape, double-size stages) ----------------
#define BM     128
#define BN     128
#define KCHUNK 64                          // build-layout chunk: 64 fp16 = 128B rows (SW128)
#define KCHUNKS (KAUG / KCHUNK)            // 66 chunks in g_Hs/g_Ws
#define BK     128                         // K per pipeline stage = 2 chunks
#define KSTEPS (KAUG / BK)                 // 33 stages of work (= 11 * NSTAGES)
#define NSTAGES 3
#define MTILES  (NUM_TOKENS / BM)          // 16
#define NTILES  (VOCAB_N / BN)             // 250

#define CH_BYTES (128 * KCHUNK * 2)        // 16384 per 64-K chunk (A and B alike)
#define STAGE_A  (2 * CH_BYTES)            // 32768
#define STAGE_B  (2 * CH_BYTES)            // 32768
#define STAGE_BYTES (STAGE_A + STAGE_B)    // 65536

#define SM_A_OFF 1024
#define SM_B_OFF (SM_A_OFF + NSTAGES * STAGE_A)     // 99328
#define SM_TOTAL (SM_B_OFF + NSTAGES * STAGE_B)     // 197632 (1 CTA/SM)

// Pre-tiled, pre-swizzled fp16 operand buffers (device-global scratch)
__device__ __align__(1024) unsigned char g_Hs[(size_t)MTILES * KCHUNKS * CH_BYTES];
__device__ __align__(1024) unsigned char g_Ws[(size_t)NTILES * KCHUNKS * CH_BYTES];

// ---------------- helpers ----------------
__device__ __forceinline__ uint32_t smem_u32(const void* p) {
    uint32_t a;
    asm("{ .reg .u64 t; cvta.to.shared.u64 t, %1; cvt.u32.u64 %0, t; }" : "=r"(a) : "l"(p));
    return a;
}
__device__ __forceinline__ uint32_t swz128(uint32_t o) { return o ^ ((o >> 3) & 0x70u); }

__device__ __forceinline__ uint32_t h2_bits(__half2 h) {
    union { __half2 h; uint32_t u; } cv;
    cv.h = h;
    return cv.u;
}

__device__ __forceinline__ bool elect1() {
    uint32_t r;
    asm volatile("{ .reg .pred p; elect.sync _|p, 0xFFFFFFFF; selp.b32 %0, 1, 0, p; }" : "=r"(r));
    return r != 0;
}

#define MBAR_INIT(addr, cnt) \
    asm volatile("mbarrier.init.shared.b64 [%0], %1;" :: "r"(addr), "r"((uint32_t)(cnt)) : "memory")

#define MBAR_EXPECT_TX(addr, bytes) \
    asm volatile("mbarrier.arrive.expect_tx.shared.b64 _, [%0], %1;" :: "r"(addr), "r"((uint32_t)(bytes)) : "memory")

#define MBAR_ARRIVE(addr) \
    asm volatile("mbarrier.arrive.shared.b64 _, [%0];" :: "r"(addr) : "memory")

#define MBAR_WAIT(addr, parity) do {                                                   \
    uint32_t _m = (addr), _p = (uint32_t)(parity), _d;                                 \
    asm volatile("{\n\t.reg .pred p;\n\t"                                              \
        "mbarrier.try_wait.parity.acquire.cta.shared::cta.b64 p, [%1], %2;\n\t"        \
        "selp.b32 %0, 1, 0, p;\n\t}"                                                   \
        : "=r"(_d) : "r"(_m), "r"(_p) : "memory");                                     \
    if (!_d) {                                                                         \
        asm volatile("{\n\t.reg .pred P1;\n\t"                                         \
            "WL_%=:\n\t"                                                               \
            "mbarrier.try_wait.parity.acquire.cta.shared::cta.b64 P1, [%0], %1, 0x989680;\n\t" \
            "@P1 bra.uni WD_%=;\n\t"                                                   \
            "bra.uni WL_%=;\n\t"                                                       \
            "WD_%=:\n\t}" :: "r"(_m), "r"(_p) : "memory");                             \
    }                                                                                  \
} while (0)

__device__ __forceinline__ void bulk_g2s(uint32_t dst, const void* src, uint32_t bytes, uint32_t mbar) {
    asm volatile(
        "cp.async.bulk.shared::cluster.global.mbarrier::complete_tx::bytes [%0], [%1], %2, [%3];"
        :: "r"(dst), "l"(src), "r"(bytes), "r"(mbar) : "memory");
}

#define LDSM_X4(r0, r1, r2, r3, addr)                                                  \
    asm volatile("ldmatrix.sync.aligned.m8n8.x4.shared.b16 {%0,%1,%2,%3}, [%4];"       \
        : "=r"(r0), "=r"(r1), "=r"(r2), "=r"(r3) : "r"(addr))

#define MMA16816(c, a0, a1, a2, a3, b0, b1)                                            \
    asm volatile("mma.sync.aligned.m16n8k16.row.col.f32.f16.f16.f32 "                  \
        "{%0,%1,%2,%3}, {%4,%5,%6,%7}, {%8,%9}, {%0,%1,%2,%3};"                        \
        : "+f"((c)[0]), "+f"((c)[1]), "+f"((c)[2]), "+f"((c)[3])                       \
        : "r"(a0), "r"(a1), "r"(a2), "r"(a3), "r"(b0), "r"(b1))

// ---------------- fused build: W' (blocks 0..15999) + H' (blocks 16000..18047) ----------------
#define WBLOCKS (VOCAB_N / 2)   // 16000

__global__ void __launch_bounds__(256) build_hw(const float* __restrict__ H,
                                                const float* __restrict__ W,
                                                const float* __restrict__ lA,
                                                const float* __restrict__ lB,
                                                const int* __restrict__ idx) {
    int bid = blockIdx.x;
    int tid = threadIdx.x;

    if (bid < WBLOCKS) {
        // ---- W' build: vocab rows 2*bid + (tid>>7), tiles of BN=128 rows ----
        int v = bid * 2 + (tid >> 7);
        int t128 = tid & 127;
        int row = v & (BN - 1);
        unsigned char* blk = g_Ws + (size_t)(v >> 7) * KCHUNKS * CH_BYTES;
        const float4* Wrow = (const float4*)(W + (size_t)v * HID);

        for (int c8 = t128; c8 < HID / 8; c8 += 128) {
            float4 f0 = Wrow[c8 * 2];
            float4 f1 = Wrow[c8 * 2 + 1];
            int c = c8 * 8;
            int ks = c >> 6, cc = c & 63;
            uint32_t o = swz128((uint32_t)(row * 128 + cc * 2));
            uint4 pk;
            pk.x = h2_bits(__floats2half2_rn(f0.x, f0.y));
            pk.y = h2_bits(__floats2half2_rn(f0.z, f0.w));
            pk.z = h2_bits(__floats2half2_rn(f1.x, f1.y));
            pk.w = h2_bits(__floats2half2_rn(f1.z, f1.w));
            *reinterpret_cast<uint4*>(blk + (size_t)ks * CH_BYTES + o) = pk;
        }
        {
            int j = t128;                    // 0..127 -> (e, r)
            int e = j >> 4, r = j & 15;
            float val = lB[((size_t)e * VOCAB_N + v) * LRANK + r];
            int col = HID + j;
            int ks = col >> 6, cc = col & 63;
            *(__half*)(blk + (size_t)ks * CH_BYTES + swz128((uint32_t)(row * 128 + cc * 2))) =
                __float2half_rn(val);
        }
        return;
    }

    // ---- H' build: one token, 256 threads ----
    int t = bid - WBLOCKS;
    int e = idx[t];
    const float* Arow = lA + (size_t)e * LRANK * HID;
    unsigned char* blk = g_Hs + (size_t)(t >> 7) * KCHUNKS * CH_BYTES;
    int row = t & 127;

    float acc[LRANK];
#pragma unroll
    for (int r = 0; r < LRANK; r++) acc[r] = 0.f;

    for (int h = tid; h < HID; h += 256) {
        float x = H[(size_t)t * HID + h];
        int ks = h >> 6, cc = h & 63;
        *(__half*)(blk + (size_t)ks * CH_BYTES + swz128((uint32_t)(row * 128 + cc * 2))) =
            __float2half_rn(x);
#pragma unroll
        for (int r = 0; r < LRANK; r++) acc[r] += x * Arow[r * HID + h];
    }

    __shared__ float wsum[8][LRANK];
    __shared__ float xa[LRANK];
    int lane = tid & 31, w = tid >> 5;
#pragma unroll
    for (int r = 0; r < LRANK; r++) {
        float v = acc[r];
        v += __shfl_down_sync(0xffffffffu, v, 16);
        v += __shfl_down_sync(0xffffffffu, v, 8);
        v += __shfl_down_sync(0xffffffffu, v, 4);
        v += __shfl_down_sync(0xffffffffu, v, 2);
        v += __shfl_down_sync(0xffffffffu, v, 1);
        if (lane == 0) wsum[w][r] = v;
    }
    __syncthreads();
    if (tid < LRANK) {
        float v = 0.f;
#pragma unroll
        for (int ww = 0; ww < 8; ww++) v += wsum[ww][tid];
        xa[tid] = v;
    }
    __syncthreads();
    if (tid < NLORA * LRANK) {
        int col = HID + tid;
        float v = ((tid >> 4) == e) ? xa[tid & 15] : 0.f;
        int ks = col >> 6, cc = col & 63;
        *(__half*)(blk + (size_t)ks * CH_BYTES + swz128((uint32_t)(row * 128 + cc * 2))) =
            __float2half_rn(v);
    }
}

// ---------------- main GEMM: out[2048,32000] = H' @ W'^T (HMMA fp16, fp32 acc) ----------------
// 288 threads: warps 0-7 compute (2x4 grid, 64x32 each), warp 8 producer. 1 CTA/SM.
// BK=128 stages (2 build chunks each): half the barrier traffic / stage crossings of R6.
// Software-pipelined double-buffered fragments + early empty-arrive at last stage read.
__global__ void __launch_bounds__(288, 1) lmhead_gemm(float* __restrict__ out) {
    extern __shared__ unsigned char smem[];
    uint32_t sb = smem_u32(smem);
    int tid = threadIdx.x, wid = tid >> 5, lane = tid & 31;
    int tile_m = blockIdx.x & (MTILES - 1);    // 16 consecutive bids share one n-tile (L2 reuse)
    int tile_n = blockIdx.x >> 4;

    uint32_t b_full  = sb + 0;     // NSTAGES x 8B
    uint32_t b_empty = sb + 64;    // NSTAGES x 8B

    if (tid == 0) {
        for (int s = 0; s < NSTAGES; s++) {
            MBAR_INIT(b_full + s * 8, 1);
            MBAR_INIT(b_empty + s * 8, 8);   // one arrive per compute warp
        }
    }
    __syncthreads();

    if (wid == 8) {
        // ---- producer (elected thread): 2 chunks of A + 2 chunks of B per stage ----
        if (elect1()) {
            const unsigned char* gA = g_Hs + (size_t)tile_m * KCHUNKS * CH_BYTES;
            const unsigned char* gB = g_Ws + (size_t)tile_n * KCHUNKS * CH_BYTES;
            int s = 0, j = 0;
            for (int i = 0; i < KSTEPS; i++) {
                if (j > 0) MBAR_WAIT(b_empty + s * 8, (j - 1) & 1);
                MBAR_EXPECT_TX(b_full + s * 8, STAGE_BYTES);
                uint32_t da = sb + SM_A_OFF + s * STAGE_A;
                uint32_t db = sb + SM_B_OFF + s * STAGE_B;
                bulk_g2s(da,            gA + (size_t)(2 * i)     * CH_BYTES, CH_BYTES, b_full + s * 8);
                bulk_g2s(da + CH_BYTES, gA + (size_t)(2 * i + 1) * CH_BYTES, CH_BYTES, b_full + s * 8);
                bulk_g2s(db,            gB + (size_t)(2 * i)     * CH_BYTES, CH_BYTES, b_full + s * 8);
                bulk_g2s(db + CH_BYTES, gB + (size_t)(2 * i + 1) * CH_BYTES, CH_BYTES, b_full + s * 8);
                if (++s == NSTAGES) { s = 0; ++j; }
            }
        }
        return;
    }

    // ---- consumers: 2x4 warp grid, each warp 64(m) x 32(n) ----
    int warp_m = wid & 1;          // 0..1 -> 64-row block
    int warp_n = wid >> 1;         // 0..3 -> 32-col block

    float acc[4][4][4];            // [mt][nt][frag]
#pragma unroll
    for (int a = 0; a < 4; a++)
#pragma unroll
        for (int b = 0; b < 4; b++)
#pragma unroll
            for (int c = 0; c < 4; c++) acc[a][b][c] = 0.f;

    int lrow = lane & 15;          // row within 16-row group
    int lhal = lane >> 4;          // 16B half selector

    uint32_t af[2][4][4];          // double-buffered A fragments
    uint32_t bf[2][2][4];          // double-buffered B fragments

// kk = 0..7 within a BK=128 stage; chunk = kk>>2, 32B k-offset within chunk = (kk&3)*32
#define LOAD_FRAGS(buf, ss, kk) do {                                                   \
    uint32_t _ab = sb + SM_A_OFF + (uint32_t)(ss) * STAGE_A + ((kk) >> 2) * CH_BYTES;  \
    uint32_t _bb = sb + SM_B_OFF + (uint32_t)(ss) * STAGE_B + ((kk) >> 2) * CH_BYTES;  \
    _Pragma("unroll")                                                                  \
    for (int _mt = 0; _mt < 4; _mt++) {                                                \
        uint32_t _o = (uint32_t)((warp_m * 64 + _mt * 16 + lrow) * 128 +               \
                                 ((kk) & 3) * 32 + lhal * 16);                         \
        LDSM_X4(af[buf][_mt][0], af[buf][_mt][1], af[buf][_mt][2], af[buf][_mt][3],    \
                _ab + swz128(_o));                                                     \
    }                                                                                  \
    _Pragma("unroll")                                                                  \
    for (int _p = 0; _p < 2; _p++) {                                                   \
        uint32_t _o = (uint32_t)((warp_n * 32 + _p * 16 + lrow) * 128 +                \
                                 ((kk) & 3) * 32 + lhal * 16);                         \
        LDSM_X4(bf[buf][_p][0], bf[buf][_p][1], bf[buf][_p][2], bf[buf][_p][3],        \
                _bb + swz128(_o));                                                     \
    }                                                                                  \
} while (0)

#define MMA_ALL(buf) do {                                                              \
    _Pragma("unroll")                                                                  \
    for (int _mt = 0; _mt < 4; _mt++) {                                                \
        _Pragma("unroll")                                                              \
        for (int _p = 0; _p < 2; _p++) {                                               \
            MMA16816(acc[_mt][_p * 2 + 0], af[buf][_mt][0], af[buf][_mt][1],           \
                     af[buf][_mt][2], af[buf][_mt][3], bf[buf][_p][0], bf[buf][_p][2]);\
            MMA16816(acc[_mt][_p * 2 + 1], af[buf][_mt][0], af[buf][_mt][1],           \
                     af[buf][_mt][2], af[buf][_mt][3], bf[buf][_p][1], bf[buf][_p][3]);\
        }                                                                              \
    }                                                                                  \
} while (0)

    // prologue: wait stage 0, load first fragments
    MBAR_WAIT(b_full + 0, 0);
    LOAD_FRAGS(0, 0, 0);

    int s = 0, ph = 0;
    for (int ks = 0; ks < KSTEPS; ks++) {
#pragma unroll
        for (int k16 = 0; k16 < 8; k16++) {
            const int cur = k16 & 1;
            const int nxt = cur ^ 1;
            if (k16 < 7) {
                LOAD_FRAGS(nxt, s, k16 + 1);           // prefetch next k-step, same stage
                if (k16 == 6 && lane == 0)             // last read of stage s issued ->
                    MBAR_ARRIVE(b_empty + s * 8);      // early release for the producer
            } else if (ks + 1 < KSTEPS) {
                int s2 = (s + 1 == NSTAGES) ? 0 : s + 1;
                int p2 = (s + 1 == NSTAGES) ? (ph ^ 1) : ph;
                MBAR_WAIT(b_full + s2 * 8, p2);        // hidden behind queued HMMAs
                LOAD_FRAGS(nxt, s2, 0);                // prefetch first k-step of next stage
            }
            MMA_ALL(cur);
        }
        if (++s == NSTAGES) { s = 0; ph ^= 1; }
    }

    // ---- epilogue: direct fp32 stores ----
    int row_base = tile_m * BM + warp_m * 64 + (lane >> 2);
    int col_base = tile_n * BN + warp_n * 32 + (lane & 3) * 2;
#pragma unroll
    for (int mt = 0; mt < 4; mt++) {
#pragma unroll
        for (int nt = 0; nt < 4; nt++) {
            int col = col_base + (nt >> 1) * 16 + (nt & 1) * 8;
            size_t r0 = (size_t)(row_base + mt * 16) * VOCAB_N + col;
            size_t r1 = r0 + 8 * VOCAB_N;
            *reinterpret_cast<float2*>(out + r0) =
                make_float2(acc[mt][nt][0], acc[mt][nt][1]);
            *reinterpret_cast<float2*>(out + r1) =
                make_float2(acc[mt][nt][2], acc[mt][nt][3]);
        }
    }
}

// ---------------- launch ----------------
extern "C" void kernel_launch(void* const* d_in, const int* in_sizes, int n_in,
                              void* d_out, int out_size) {
    const float* H   = (const float*)d_in[0];   // [2048, 4096]
    const float* W   = (const float*)d_in[1];   // [32000, 4096]
    const float* lA  = (const float*)d_in[2];   // [8, 16, 4096]
    const float* lB  = (const float*)d_in[3];   // [8, 32000, 16]
    const int*   idx = (const int*)d_in[4];     // [2048]
    float* out = (float*)d_out;                 // [2048, 32000]

    cudaFuncSetAttribute(lmhead_gemm, cudaFuncAttributeMaxDynamicSharedMemorySize, SM_TOTAL);

    build_hw<<<WBLOCKS + NUM_TOKENS, 256>>>(H, W, lA, lB, idx);
    lmhead_gemm<<<MTILES * NTILES, 288, SM_TOTAL>>>(out);
}

// round 15
// speedup vs baseline: 1.0600x; 1.0182x over previous
#include <cuda_runtime.h>
#include <cuda_fp16.h>
#include <cstdint>
#include <cstddef>

// ---------------- problem dims ----------------
#define NUM_TOKENS 2048
#define HID        4096
#define NLORA      8
#define LRANK      16
#define VOCAB_N    32000
#define KAUG       (HID + NLORA * LRANK)   // 4224

// ---------------- GEMM tiling (R14 proven config — unchanged) ----------------
#define BM     128
#define BN     128
#define KCHUNK 64                          // build-layout chunk: 64 fp16 = 128B rows (SW128)
#define KCHUNKS (KAUG / KCHUNK)            // 66 chunks in g_Hs/g_Ws
#define BK     128                         // K per pipeline stage = 2 chunks
#define KSTEPS (KAUG / BK)                 // 33 stages of work (= 11 * NSTAGES)
#define NSTAGES 3
#define MTILES  (NUM_TOKENS / BM)          // 16
#define NTILES  (VOCAB_N / BN)             // 250

#define CH_BYTES (128 * KCHUNK * 2)        // 16384 per 64-K chunk (A and B alike)
#define STAGE_A  (2 * CH_BYTES)            // 32768
#define STAGE_B  (2 * CH_BYTES)            // 32768
#define STAGE_BYTES (STAGE_A + STAGE_B)    // 65536

#define SM_A_OFF 1024
#define SM_B_OFF (SM_A_OFF + NSTAGES * STAGE_A)     // 99328
#define SM_TOTAL (SM_B_OFF + NSTAGES * STAGE_B)     // 197632 (1 CTA/SM)

// Pre-tiled, pre-swizzled fp16 operand buffers (device-global scratch)
__device__ __align__(1024) unsigned char g_Hs[(size_t)MTILES * KCHUNKS * CH_BYTES];
__device__ __align__(1024) unsigned char g_Ws[(size_t)NTILES * KCHUNKS * CH_BYTES];

// ---------------- helpers ----------------
__device__ __forceinline__ uint32_t smem_u32(const void* p) {
    uint32_t a;
    asm("{ .reg .u64 t; cvta.to.shared.u64 t, %1; cvt.u32.u64 %0, t; }" : "=r"(a) : "l"(p));
    return a;
}
__device__ __forceinline__ uint32_t swz128(uint32_t o) { return o ^ ((o >> 3) & 0x70u); }

__device__ __forceinline__ uint32_t h2_bits(__half2 h) {
    union { __half2 h; uint32_t u; } cv;
    cv.h = h;
    return cv.u;
}

__device__ __forceinline__ bool elect1() {
    uint32_t r;
    asm volatile("{ .reg .pred p; elect.sync _|p, 0xFFFFFFFF; selp.b32 %0, 1, 0, p; }" : "=r"(r));
    return r != 0;
}

#define MBAR_INIT(addr, cnt) \
    asm volatile("mbarrier.init.shared.b64 [%0], %1;" :: "r"(addr), "r"((uint32_t)(cnt)) : "memory")

#define MBAR_EXPECT_TX(addr, bytes) \
    asm volatile("mbarrier.arrive.expect_tx.shared.b64 _, [%0], %1;" :: "r"(addr), "r"((uint32_t)(bytes)) : "memory")

#define MBAR_ARRIVE(addr) \
    asm volatile("mbarrier.arrive.shared.b64 _, [%0];" :: "r"(addr) : "memory")

#define MBAR_WAIT(addr, parity) do {                                                   \
    uint32_t _m = (addr), _p = (uint32_t)(parity), _d;                                 \
    asm volatile("{\n\t.reg .pred p;\n\t"                                              \
        "mbarrier.try_wait.parity.acquire.cta.shared::cta.b64 p, [%1], %2;\n\t"        \
        "selp.b32 %0, 1, 0, p;\n\t}"                                                   \
        : "=r"(_d) : "r"(_m), "r"(_p) : "memory");                                     \
    if (!_d) {                                                                         \
        asm volatile("{\n\t.reg .pred P1;\n\t"                                         \
            "WL_%=:\n\t"                                                               \
            "mbarrier.try_wait.parity.acquire.cta.shared::cta.b64 P1, [%0], %1, 0x989680;\n\t" \
            "@P1 bra.uni WD_%=;\n\t"                                                   \
            "bra.uni WL_%=;\n\t"                                                       \
            "WD_%=:\n\t}" :: "r"(_m), "r"(_p) : "memory");                             \
    }                                                                                  \
} while (0)

__device__ __forceinline__ void bulk_g2s(uint32_t dst, const void* src, uint32_t bytes, uint32_t mbar) {
    asm volatile(
        "cp.async.bulk.shared::cluster.global.mbarrier::complete_tx::bytes [%0], [%1], %2, [%3];"
        :: "r"(dst), "l"(src), "r"(bytes), "r"(mbar) : "memory");
}

#define LDSM_X4(r0, r1, r2, r3, addr)                                                  \
    asm volatile("ldmatrix.sync.aligned.m8n8.x4.shared.b16 {%0,%1,%2,%3}, [%4];"       \
        : "=r"(r0), "=r"(r1), "=r"(r2), "=r"(r3) : "r"(addr))

#define MMA16816(c, a0, a1, a2, a3, b0, b1)                                            \
    asm volatile("mma.sync.aligned.m16n8k16.row.col.f32.f16.f16.f32 "                  \
        "{%0,%1,%2,%3}, {%4,%5,%6,%7}, {%8,%9}, {%0,%1,%2,%3};"                        \
        : "+f"((c)[0]), "+f"((c)[1]), "+f"((c)[2]), "+f"((c)[3])                       \
        : "r"(a0), "r"(a1), "r"(a2), "r"(a3), "r"(b0), "r"(b1))

// ---------------- fused build with INTERLEAVED H/W blocks ----------------
// Groups of 8 bids = 7 W-blocks + 1 H-block for the first 16384 bids, so the
// L2-bound XA reduction (lora_A re-reads) overlaps the DRAM-bound W rewrite
// instead of running as a serial tail. Remaining bids are W-only.
#define WBLOCKS  (VOCAB_N / 2)             // 16000
#define NBLOCKS  (WBLOCKS + NUM_TOKENS)    // 18048

__global__ void __launch_bounds__(256) build_hw(const float* __restrict__ H,
                                                const float* __restrict__ W,
                                                const float* __restrict__ lA,
                                                const float* __restrict__ lB,
                                                const int* __restrict__ idx) {
    int bid = blockIdx.x;
    int tid = threadIdx.x;

    int h_token = -1;   // >=0 -> this block builds H' for that token
    int wi = 0;         // else W block index
    if (bid < 16384) {
        int g = bid >> 3, sl = bid & 7;
        if (sl == 7) h_token = g;            // g in [0, 2048)
        else         wi = g * 7 + sl;        // [0, 14336)
    } else {
        wi = 14336 + (bid - 16384);          // [14336, 16000)
    }

    if (h_token < 0) {
        // ---- W' build: vocab rows 2*wi + (tid>>7), tiles of BN=128 rows ----
        int v = wi * 2 + (tid >> 7);
        int t128 = tid & 127;
        int row = v & (BN - 1);
        unsigned char* blk = g_Ws + (size_t)(v >> 7) * KCHUNKS * CH_BYTES;
        const float4* Wrow = (const float4*)(W + (size_t)v * HID);

        for (int c8 = t128; c8 < HID / 8; c8 += 128) {
            float4 f0 = Wrow[c8 * 2];
            float4 f1 = Wrow[c8 * 2 + 1];
            int c = c8 * 8;
            int ks = c >> 6, cc = c & 63;
            uint32_t o = swz128((uint32_t)(row * 128 + cc * 2));
            uint4 pk;
            pk.x = h2_bits(__floats2half2_rn(f0.x, f0.y));
            pk.y = h2_bits(__floats2half2_rn(f0.z, f0.w));
            pk.z = h2_bits(__floats2half2_rn(f1.x, f1.y));
            pk.w = h2_bits(__floats2half2_rn(f1.z, f1.w));
            *reinterpret_cast<uint4*>(blk + (size_t)ks * CH_BYTES + o) = pk;
        }
        {
            int j = t128;                    // 0..127 -> (e, r)
            int e = j >> 4, r = j & 15;
            float val = lB[((size_t)e * VOCAB_N + v) * LRANK + r];
            int col = HID + j;
            int ks = col >> 6, cc = col & 63;
            *(__half*)(blk + (size_t)ks * CH_BYTES + swz128((uint32_t)(row * 128 + cc * 2))) =
                __float2half_rn(val);
        }
        return;
    }

    // ---- H' build: one token, 256 threads ----
    int t = h_token;
    int e = idx[t];
    const float* Arow = lA + (size_t)e * LRANK * HID;
    unsigned char* blk = g_Hs + (size_t)(t >> 7) * KCHUNKS * CH_BYTES;
    int row = t & 127;

    float acc[LRANK];
#pragma unroll
    for (int r = 0; r < LRANK; r++) acc[r] = 0.f;

    for (int h = tid; h < HID; h += 256) {
        float x = H[(size_t)t * HID + h];
        int ks = h >> 6, cc = h & 63;
        *(__half*)(blk + (size_t)ks * CH_BYTES + swz128((uint32_t)(row * 128 + cc * 2))) =
            __float2half_rn(x);
#pragma unroll
        for (int r = 0; r < LRANK; r++) acc[r] += x * Arow[r * HID + h];
    }

    __shared__ float wsum[8][LRANK];
    __shared__ float xa[LRANK];
    int lane = tid & 31, w = tid >> 5;
#pragma unroll
    for (int r = 0; r < LRANK; r++) {
        float v = acc[r];
        v += __shfl_down_sync(0xffffffffu, v, 16);
        v += __shfl_down_sync(0xffffffffu, v, 8);
        v += __shfl_down_sync(0xffffffffu, v, 4);
        v += __shfl_down_sync(0xffffffffu, v, 2);
        v += __shfl_down_sync(0xffffffffu, v, 1);
        if (lane == 0) wsum[w][r] = v;
    }
    __syncthreads();
    if (tid < LRANK) {
        float v = 0.f;
#pragma unroll
        for (int ww = 0; ww < 8; ww++) v += wsum[ww][tid];
        xa[tid] = v;
    }
    __syncthreads();
    if (tid < NLORA * LRANK) {
        int col = HID + tid;
        float v = ((tid >> 4) == e) ? xa[tid & 15] : 0.f;
        int ks = col >> 6, cc = col & 63;
        *(__half*)(blk + (size_t)ks * CH_BYTES + swz128((uint32_t)(row * 128 + cc * 2))) =
            __float2half_rn(v);
    }
}

// ---------------- main GEMM: out[2048,32000] = H' @ W'^T (HMMA fp16, fp32 acc) ----------------
// R14 kernel, unchanged: 288 threads, 8 compute warps (2x4, 64x32 each) + producer warp.
// BK=128 stages, software-pipelined double-buffered fragments, early empty-arrive.
__global__ void __launch_bounds__(288, 1) lmhead_gemm(float* __restrict__ out) {
    extern __shared__ unsigned char smem[];
    uint32_t sb = smem_u32(smem);
    int tid = threadIdx.x, wid = tid >> 5, lane = tid & 31;
    int tile_m = blockIdx.x & (MTILES - 1);    // 16 consecutive bids share one n-tile (L2 reuse)
    int tile_n = blockIdx.x >> 4;

    uint32_t b_full  = sb + 0;     // NSTAGES x 8B
    uint32_t b_empty = sb + 64;    // NSTAGES x 8B

    if (tid == 0) {
        for (int s = 0; s < NSTAGES; s++) {
            MBAR_INIT(b_full + s * 8, 1);
            MBAR_INIT(b_empty + s * 8, 8);   // one arrive per compute warp
        }
    }
    __syncthreads();

    if (wid == 8) {
        // ---- producer (elected thread): 2 chunks of A + 2 chunks of B per stage ----
        if (elect1()) {
            const unsigned char* gA = g_Hs + (size_t)tile_m * KCHUNKS * CH_BYTES;
            const unsigned char* gB = g_Ws + (size_t)tile_n * KCHUNKS * CH_BYTES;
            int s = 0, j = 0;
            for (int i = 0; i < KSTEPS; i++) {
                if (j > 0) MBAR_WAIT(b_empty + s * 8, (j - 1) & 1);
                MBAR_EXPECT_TX(b_full + s * 8, STAGE_BYTES);
                uint32_t da = sb + SM_A_OFF + s * STAGE_A;
                uint32_t db = sb + SM_B_OFF + s * STAGE_B;
                bulk_g2s(da,            gA + (size_t)(2 * i)     * CH_BYTES, CH_BYTES, b_full + s * 8);
                bulk_g2s(da + CH_BYTES, gA + (size_t)(2 * i + 1) * CH_BYTES, CH_BYTES, b_full + s * 8);
                bulk_g2s(db,            gB + (size_t)(2 * i)     * CH_BYTES, CH_BYTES, b_full + s * 8);
                bulk_g2s(db + CH_BYTES, gB + (size_t)(2 * i + 1) * CH_BYTES, CH_BYTES, b_full + s * 8);
                if (++s == NSTAGES) { s = 0; ++j; }
            }
        }
        return;
    }

    // ---- consumers: 2x4 warp grid, each warp 64(m) x 32(n) ----
    int warp_m = wid & 1;          // 0..1 -> 64-row block
    int warp_n = wid >> 1;         // 0..3 -> 32-col block

    float acc[4][4][4];            // [mt][nt][frag]
#pragma unroll
    for (int a = 0; a < 4; a++)
#pragma unroll
        for (int b = 0; b < 4; b++)
#pragma unroll
            for (int c = 0; c < 4; c++) acc[a][b][c] = 0.f;

    int lrow = lane & 15;          // row within 16-row group
    int lhal = lane >> 4;          // 16B half selector

    uint32_t af[2][4][4];          // double-buffered A fragments
    uint32_t bf[2][2][4];          // double-buffered B fragments

// kk = 0..7 within a BK=128 stage; chunk = kk>>2, 32B k-offset within chunk = (kk&3)*32
#define LOAD_FRAGS(buf, ss, kk) do {                                                   \
    uint32_t _ab = sb + SM_A_OFF + (uint32_t)(ss) * STAGE_A + ((kk) >> 2) * CH_BYTES;  \
    uint32_t _bb = sb + SM_B_OFF + (uint32_t)(ss) * STAGE_B + ((kk) >> 2) * CH_BYTES;  \
    _Pragma("unroll")                                                                  \
    for (int _mt = 0; _mt < 4; _mt++) {                                                \
        uint32_t _o = (uint32_t)((warp_m * 64 + _mt * 16 + lrow) * 128 +               \
                                 ((kk) & 3) * 32 + lhal * 16);                         \
        LDSM_X4(af[buf][_mt][0], af[buf][_mt][1], af[buf][_mt][2], af[buf][_mt][3],    \
                _ab + swz128(_o));                                                     \
    }                                                                                  \
    _Pragma("unroll")                                                                  \
    for (int _p = 0; _p < 2; _p++) {                                                   \
        uint32_t _o = (uint32_t)((warp_n * 32 + _p * 16 + lrow) * 128 +                \
                                 ((kk) & 3) * 32 + lhal * 16);                         \
        LDSM_X4(bf[buf][_p][0], bf[buf][_p][1], bf[buf][_p][2], bf[buf][_p][3],        \
                _bb + swz128(_o));                                                     \
    }                                                                                  \
} while (0)

#define MMA_ALL(buf) do {                                                              \
    _Pragma("unroll")                                                                  \
    for (int _mt = 0; _mt < 4; _mt++) {                                                \
        _Pragma("unroll")                                                              \
        for (int _p = 0; _p < 2; _p++) {                                               \
            MMA16816(acc[_mt][_p * 2 + 0], af[buf][_mt][0], af[buf][_mt][1],           \
                     af[buf][_mt][2], af[buf][_mt][3], bf[buf][_p][0], bf[buf][_p][2]);\
            MMA16816(acc[_mt][_p * 2 + 1], af[buf][_mt][0], af[buf][_mt][1],           \
                     af[buf][_mt][2], af[buf][_mt][3], bf[buf][_p][1], bf[buf][_p][3]);\
        }                                                                              \
    }                                                                                  \
} while (0)

    // prologue: wait stage 0, load first fragments
    MBAR_WAIT(b_full + 0, 0);
    LOAD_FRAGS(0, 0, 0);

    int s = 0, ph = 0;
    for (int ks = 0; ks < KSTEPS; ks++) {
#pragma unroll
        for (int k16 = 0; k16 < 8; k16++) {
            const int cur = k16 & 1;
            const int nxt = cur ^ 1;
            if (k16 < 7) {
                LOAD_FRAGS(nxt, s, k16 + 1);           // prefetch next k-step, same stage
                if (k16 == 6 && lane == 0)             // last read of stage s issued ->
                    MBAR_ARRIVE(b_empty + s * 8);      // early release for the producer
            } else if (ks + 1 < KSTEPS) {
                int s2 = (s + 1 == NSTAGES) ? 0 : s + 1;
                int p2 = (s + 1 == NSTAGES) ? (ph ^ 1) : ph;
                MBAR_WAIT(b_full + s2 * 8, p2);        // hidden behind queued HMMAs
                LOAD_FRAGS(nxt, s2, 0);                // prefetch first k-step of next stage
            }
            MMA_ALL(cur);
        }
        if (++s == NSTAGES) { s = 0; ph ^= 1; }
    }

    // ---- epilogue: direct fp32 stores ----
    int row_base = tile_m * BM + warp_m * 64 + (lane >> 2);
    int col_base = tile_n * BN + warp_n * 32 + (lane & 3) * 2;
#pragma unroll
    for (int mt = 0; mt < 4; mt++) {
#pragma unroll
        for (int nt = 0; nt < 4; nt++) {
            int col = col_base + (nt >> 1) * 16 + (nt & 1) * 8;
            size_t r0 = (size_t)(row_base + mt * 16) * VOCAB_N + col;
            size_t r1 = r0 + 8 * VOCAB_N;
            *reinterpret_cast<float2*>(out + r0) =
                make_float2(acc[mt][nt][0], acc[mt][nt][1]);
            *reinterpret_cast<float2*>(out + r1) =
                make_float2(acc[mt][nt][2], acc[mt][nt][3]);
        }
    }
}

// ---------------- launch ----------------
extern "C" void kernel_launch(void* const* d_in, const int* in_sizes, int n_in,
                              void* d_out, int out_size) {
    const float* H   = (const float*)d_in[0];   // [2048, 4096]
    const float* W   = (const float*)d_in[1];   // [32000, 4096]
    const float* lA  = (const float*)d_in[2];   // [8, 16, 4096]
    const float* lB  = (const float*)d_in[3];   // [8, 32000, 16]
    const int*   idx = (const int*)d_in[4];     // [2048]
    float* out = (float*)d_out;                 // [2048, 32000]

    cudaFuncSetAttribute(lmhead_gemm, cudaFuncAttributeMaxDynamicSharedMemorySize, SM_TOTAL);

    build_hw<<<NBLOCKS, 256>>>(H, W, lA, lB, idx);
    lmhead_gemm<<<MTILES * NTILES, 288, SM_TOTAL>>>(out);
}